// round 12
// baseline (speedup 1.0000x reference)
#include <cuda_runtime.h>
#include <cuda_bf16.h>

// out[n,p,:] = feat[n,p,:] * mean_m task[n,m,p]
// n=32, m=16, p=1024, d=512 (fp32)
//
// R11 winner (dur 18.9us, kernel 18.2us = ~7.4 TB/s aggregate, at the
// mixed-stream roofline). Settled config from the R4-R11 matrix:
//  - float4 (128-bit) feat loads, DEFAULT policy (__ldg)
//      (v8 loads: faster cold, ~2.5us slower in steady-state replays;
//       .cs loads: always slower)
//  - __stcs (evict-first) stores: out never re-read
//  - warp-autonomous: 2 rows/warp, means via width-16 shfl reduce;
//    no smem, no block barriers
// This round: A/B store pairs interleaved (starts drain 1 shuffle earlier);
// otherwise identical — doubles as the reproducibility re-bench.

#define N_ 32
#define M_ 16
#define P_ 1024
#define D_ 512

#define TPB_ 256
#define ROWS_PER_BLK_ 16   // 8 warps x 2 rows

__global__ __launch_bounds__(TPB_, 8)
void MAP_fused_kernel(const float* __restrict__ task,
                      const float* __restrict__ feat,
                      float* __restrict__ out) {
    const int tid  = threadIdx.x;
    const int warp = tid >> 5;
    const int lane = tid & 31;

    const int rowA = blockIdx.x * ROWS_PER_BLK_ + warp * 2;  // global row n*P_+p
    const int n  = rowA >> 10;           // same n for the whole block (16 | 1024)
    const int p0 = rowA & (P_ - 1);

    // ---- task load (issued first: feeds the shuffle chain) ----
    const int m = lane & 15;             // 0..15
    const int pr = p0 + (lane >> 4);     // row A for lanes 0-15, row B for 16-31
    float tv = __ldg(task + (size_t)n * (M_ * P_) + m * P_ + pr);

    // ---- feat loads (default policy; overlap task latency) ----
    const float4* f4 = reinterpret_cast<const float4*>(feat);
    float4*       o4 = reinterpret_cast<float4*>(out);
    const size_t a = (size_t)rowA * (D_ / 4) + lane;   // row A, this lane
    float4 va[4], vb[4];
#pragma unroll
    for (int j = 0; j < 4; ++j)
        va[j] = __ldg(f4 + a + j * 32);
#pragma unroll
    for (int j = 0; j < 4; ++j)
        vb[j] = __ldg(f4 + a + (D_ / 4) + j * 32);

    // ---- segment reduce (width 16) -> both row means on every lane ----
    tv += __shfl_xor_sync(0xffffffffu, tv, 8, 16);
    tv += __shfl_xor_sync(0xffffffffu, tv, 4, 16);
    tv += __shfl_xor_sync(0xffffffffu, tv, 2, 16);
    tv += __shfl_xor_sync(0xffffffffu, tv, 1, 16);
    const float muA = __shfl_sync(0xffffffffu, tv, 0)  * (1.0f / (float)M_);
    const float muB = __shfl_sync(0xffffffffu, tv, 16) * (1.0f / (float)M_);

    // ---- scale + store (evict-first), A/B interleaved ----
#pragma unroll
    for (int j = 0; j < 4; ++j) {
        float4 r;
        r.x = va[j].x * muA; r.y = va[j].y * muA;
        r.z = va[j].z * muA; r.w = va[j].w * muA;
        __stcs(o4 + a + j * 32, r);

        float4 s;
        s.x = vb[j].x * muB; s.y = vb[j].y * muB;
        s.z = vb[j].z * muB; s.w = vb[j].w * muB;
        __stcs(o4 + a + (D_ / 4) + j * 32, s);
    }
}

extern "C" void kernel_launch(void* const* d_in, const int* in_sizes, int n_in,
                              void* d_out, int out_size) {
    const float* task = (const float*)d_in[0];   // [32,16,1024]
    const float* feat = (const float*)d_in[1];   // [32,1024,512]
    float* out = (float*)d_out;                  // [32,1024,512]
    (void)in_sizes; (void)n_in; (void)out_size;

    const unsigned blocks = (N_ * P_) / ROWS_PER_BLK_;   // 2048
    MAP_fused_kernel<<<blocks, TPB_>>>(task, feat, out);
}